// round 15
// baseline (speedup 1.0000x reference)
#include <cuda_runtime.h>
#include <cuda_fp16.h>
#include <math.h>
#include <stdint.h>

#define S_LEN 4096
#define DMODEL 768
#define NH 12
#define DK 64
#define XN (S_LEN * DMODEL)
#define WN (DMODEL * DMODEL)

__device__ __half g_xh[3 * XN];
__device__ __half g_wh[2 * WN], g_wl[2 * WN];
__device__ __half g_qh[XN], g_kh[XN], g_vh[XN];
__device__ __half g_ah[XN];

__device__ __forceinline__ uint32_t smem_u32(const void* p) {
    uint32_t a;
    asm("{ .reg .u64 t; cvta.to.shared.u64 t, %1; cvt.u32.u64 %0, t; }" : "=r"(a) : "l"(p));
    return a;
}
__device__ __forceinline__ float ex2f(float x) {
    float r; asm("ex2.approx.ftz.f32 %0, %1;" : "=f"(r) : "f"(x)); return r;
}
__device__ __forceinline__ uint32_t pack_f16(float a, float b) {  // low=a, high=b
    __half2 h = __floats2half2_rn(a, b);
    return *(uint32_t*)&h;
}
__device__ __forceinline__ void ldsm4(uint32_t* r, uint32_t a) {
    asm volatile("ldmatrix.sync.aligned.m8n8.x4.shared.b16 {%0,%1,%2,%3}, [%4];"
                 : "=r"(r[0]), "=r"(r[1]), "=r"(r[2]), "=r"(r[3]) : "r"(a));
}
__device__ __forceinline__ void ldsm4t(uint32_t* r, uint32_t a) {
    asm volatile("ldmatrix.sync.aligned.m8n8.x4.trans.shared.b16 {%0,%1,%2,%3}, [%4];"
                 : "=r"(r[0]), "=r"(r[1]), "=r"(r[2]), "=r"(r[3]) : "r"(a));
}
__device__ __forceinline__ void mma16816(float* d, const uint32_t* a, const uint32_t* b) {
    asm volatile("mma.sync.aligned.m16n8k16.row.col.f32.f16.f16.f32 "
                 "{%0,%1,%2,%3}, {%4,%5,%6,%7}, {%8,%9}, {%0,%1,%2,%3};"
                 : "+f"(d[0]), "+f"(d[1]), "+f"(d[2]), "+f"(d[3])
                 : "r"(a[0]), "r"(a[1]), "r"(a[2]), "r"(a[3]), "r"(b[0]), "r"(b[1]));
}
__device__ __forceinline__ void cp16(uint32_t d, const void* s) {
    asm volatile("cp.async.cg.shared.global [%0], [%1], 16;" :: "r"(d), "l"(s));
}
#define CP_COMMIT() asm volatile("cp.async.commit_group;" ::: "memory")
#define CP_WAIT0()  asm volatile("cp.async.wait_group 0;" ::: "memory")
#define CP_WAIT1()  asm volatile("cp.async.wait_group 1;" ::: "memory")

// fp32 -> fp16 (hi only), 3 tensors via grid.z
__global__ void conv_hi3(const float* __restrict__ a, const float* __restrict__ b,
                         const float* __restrict__ c, __half* __restrict__ hi, int n4)
{
    int i = blockIdx.x * blockDim.x + threadIdx.x;
    if (i >= n4) return;
    const float* in = (blockIdx.z == 0) ? a : (blockIdx.z == 1) ? b : c;
    size_t off = (size_t)blockIdx.z * n4 + i;
    float4 v = ((const float4*)in)[i];
    ((__half2*)hi)[2 * off]     = __floats2half2_rn(v.x, v.y);
    ((__half2*)hi)[2 * off + 1] = __floats2half2_rn(v.z, v.w);
}
// fp32 -> fp16 hi+lo, 2 tensors via grid.z (weights; lo needed for Wo)
__global__ void conv_hilo2(const float* __restrict__ a, const float* __restrict__ b,
                           __half* __restrict__ hi, __half* __restrict__ lo, int n4)
{
    int i = blockIdx.x * blockDim.x + threadIdx.x;
    if (i >= n4) return;
    const float* in = (blockIdx.z == 0) ? a : b;
    size_t off = (size_t)blockIdx.z * n4 + i;
    float4 v = ((const float4*)in)[i];
    __half2 h01 = __floats2half2_rn(v.x, v.y), h23 = __floats2half2_rn(v.z, v.w);
    ((__half2*)hi)[2 * off] = h01; ((__half2*)hi)[2 * off + 1] = h23;
    ((__half2*)lo)[2 * off]     = __floats2half2_rn(v.x - __half2float(h01.x), v.y - __half2float(h01.y));
    ((__half2*)lo)[2 * off + 1] = __floats2half2_rn(v.z - __half2float(h23.x), v.w - __half2float(h23.y));
}

// ---------------------------------------------------------------------------
// QKV projection: SINGLE-pass fp16 GEMM, 2 matrices per stage [X | W].
// ---------------------------------------------------------------------------
#define PM 5120
#define P1STG (2 * PM)
#define QKV_SMEM (2 * P1STG * 2)   // 40960 B

__device__ __forceinline__ void qkv_stage_load(
    __half* st, const __half* X, const __half* W, int m0, int n0, int k0, int tid)
{
    #pragma unroll
    for (int i = 0; i < 2; i++) {
        int idx = tid + i * 256;
        int r = idx >> 2, c8 = (idx & 3) * 8;
        uint32_t base = smem_u32(st + r * 40 + c8);
        cp16(base,          X + (size_t)(m0 + r) * DMODEL + k0 + c8);
        cp16(base + PM * 2, W + (size_t)(n0 + r) * DMODEL + k0 + c8);
    }
    CP_COMMIT();
}

__global__ void __launch_bounds__(256, 2) qkv_proj(
    const __half* __restrict__ xh, const __half* __restrict__ Wh,
    const float* __restrict__ bias,
    __half* __restrict__ Qh, __half* __restrict__ Kh, __half* __restrict__ Vh)
{
    extern __shared__ __half sm[];
    const int tid = threadIdx.x, w = tid >> 5, lid = tid & 31;
    const int wm = w >> 1, wn = w & 1;
    const int m0 = blockIdx.y * 128, n0 = blockIdx.x * 128, z = blockIdx.z;
    const __half* X = xh + (size_t)z * XN;
    __half* Yh = (z == 0) ? Qh : (z == 1) ? Kh : Vh;
    const float sc = (z == 0) ? 0.18033688011112042f : 1.0f;  // 0.125*log2(e)

    float acc[2][8][4] = {};
    qkv_stage_load(sm, X, Wh, m0, n0, 0, tid);
    for (int t = 0; t < DMODEL / 32; t++) {
        CP_WAIT0();
        __syncthreads();
        if (t + 1 < DMODEL / 32)
            qkv_stage_load(sm + ((t + 1) & 1) * P1STG, X, Wh, m0, n0, (t + 1) * 32, tid);
        __half* P0 = sm + (t & 1) * P1STG;
        __half* P1 = P0 + PM;
        #pragma unroll
        for (int ks = 0; ks < 32; ks += 16) {
            const int ac = ks + ((lid >> 4) << 3);
            uint32_t a1[2][4], b1[8][2], r4[4];
            #pragma unroll
            for (int jp = 0; jp < 4; jp++) {
                int rB = 64 * wn + 16 * jp + (lid & 15);
                ldsm4(r4, smem_u32(P1 + rB * 40 + ac));
                b1[2*jp][0]=r4[0]; b1[2*jp][1]=r4[2]; b1[2*jp+1][0]=r4[1]; b1[2*jp+1][1]=r4[3];
            }
            #pragma unroll
            for (int i = 0; i < 2; i++) {
                int rA = 32 * wm + 16 * i + (lid & 15);
                ldsm4(a1[i], smem_u32(P0 + rA * 40 + ac));
            }
            #pragma unroll
            for (int i = 0; i < 2; i++)
                #pragma unroll
                for (int j = 0; j < 8; j++) mma16816(acc[i][j], a1[i], b1[j]);
        }
        __syncthreads();
    }

    #pragma unroll
    for (int i = 0; i < 2; i++) {
        int r = m0 + 32 * wm + 16 * i + (lid >> 2);
        #pragma unroll
        for (int j = 0; j < 8; j++) {
            int ng = n0 + 64 * wn + 8 * j + (lid & 3) * 2;
            float b0 = bias[ng], b1 = bias[ng + 1];
            int head = ng >> 6;
            #pragma unroll
            for (int hrow = 0; hrow < 2; hrow++) {
                int rr = r + hrow * 8;
                float f0 = (acc[i][j][2*hrow]   + b0) * sc;
                float f1 = (acc[i][j][2*hrow+1] + b1) * sc;
                size_t dst = ((size_t)head * S_LEN + rr) * DK + (ng & 63);
                *(uint32_t*)(Yh + dst) = pack_f16(f0, f1);
            }
        }
    }
}

// ---------------------------------------------------------------------------
// Output projection: 2-pass Ah·(Wh+Wl), 3 matrices per stage.
// ---------------------------------------------------------------------------
#define PSTG (3 * PM)
#define PROJ_SMEM (2 * PSTG * 2)   // 61440 B

__device__ __forceinline__ void out_stage_load(
    __half* st, const __half* A, const __half* Wh, const __half* Wl,
    int m0, int n0, int k0, int tid)
{
    #pragma unroll
    for (int i = 0; i < 2; i++) {
        int idx = tid + i * 256;
        int r = idx >> 2, c8 = (idx & 3) * 8;
        size_t ms = (size_t)(m0 + r) * DMODEL + k0 + c8;
        size_t ns = (size_t)(n0 + r) * DMODEL + k0 + c8;
        uint32_t base = smem_u32(st + r * 40 + c8);
        cp16(base,              A + ms);
        cp16(base + PM * 2,     Wh + ns);
        cp16(base + 2 * PM * 2, Wl + ns);
    }
    CP_COMMIT();
}

__global__ void __launch_bounds__(256, 2) out_proj(
    const __half* __restrict__ Ah,
    const __half* __restrict__ Wh, const __half* __restrict__ Wl,
    const float* __restrict__ bias, float* __restrict__ Yf)
{
    extern __shared__ __half sm[];
    const int tid = threadIdx.x, w = tid >> 5, lid = tid & 31;
    const int wm = w >> 1, wn = w & 1;
    const int m0 = blockIdx.y * 128, n0 = blockIdx.x * 128;

    float acc[2][8][4] = {};
    out_stage_load(sm, Ah, Wh, Wl, m0, n0, 0, tid);
    for (int t = 0; t < DMODEL / 32; t++) {
        CP_WAIT0();
        __syncthreads();
        if (t + 1 < DMODEL / 32)
            out_stage_load(sm + ((t + 1) & 1) * PSTG, Ah, Wh, Wl, m0, n0, (t + 1) * 32, tid);
        __half* P0 = sm + (t & 1) * PSTG;
        __half* P1 = P0 + PM;
        __half* P2 = P0 + 2 * PM;
        #pragma unroll
        for (int ks = 0; ks < 32; ks += 16) {
            const int ac = ks + ((lid >> 4) << 3);
            uint32_t a1[2][4], b1[8][2], b2[8][2], r4[4];
            #pragma unroll
            for (int jp = 0; jp < 4; jp++) {
                int rB = 64 * wn + 16 * jp + (lid & 15);
                ldsm4(r4, smem_u32(P1 + rB * 40 + ac));
                b1[2*jp][0]=r4[0]; b1[2*jp][1]=r4[2]; b1[2*jp+1][0]=r4[1]; b1[2*jp+1][1]=r4[3];
                ldsm4(r4, smem_u32(P2 + rB * 40 + ac));
                b2[2*jp][0]=r4[0]; b2[2*jp][1]=r4[2]; b2[2*jp+1][0]=r4[1]; b2[2*jp+1][1]=r4[3];
            }
            #pragma unroll
            for (int i = 0; i < 2; i++) {
                int rA = 32 * wm + 16 * i + (lid & 15);
                ldsm4(a1[i], smem_u32(P0 + rA * 40 + ac));
            }
            #pragma unroll
            for (int i = 0; i < 2; i++) {
                #pragma unroll
                for (int j = 0; j < 8; j++) mma16816(acc[i][j], a1[i], b1[j]);
                #pragma unroll
                for (int j = 0; j < 8; j++) mma16816(acc[i][j], a1[i], b2[j]);
            }
        }
        __syncthreads();
    }

    #pragma unroll
    for (int i = 0; i < 2; i++) {
        int r = m0 + 32 * wm + 16 * i + (lid >> 2);
        #pragma unroll
        for (int j = 0; j < 8; j++) {
            int ng = n0 + 64 * wn + 8 * j + (lid & 3) * 2;
            float b0 = bias[ng], b1 = bias[ng + 1];
            #pragma unroll
            for (int hrow = 0; hrow < 2; hrow++) {
                int rr = r + hrow * 8;
                Yf[(size_t)rr * DMODEL + ng]     = acc[i][j][2*hrow]   + b0;
                Yf[(size_t)rr * DMODEL + ng + 1] = acc[i][j][2*hrow+1] + b1;
            }
        }
    }
}

// ---------------------------------------------------------------------------
// Flash attention: CTA=(head, 128 q rows), 8 warps, Bc=64, fp16.
// S = Qh·Kh (1 pass); softmax exp in fp16x2 (h2exp2); O = Ph·Vh (1 pass).
// 3-stage cp.async [Kh 64|Vh 64]; stage 2 overlays dead Q rows. smem 54KB.
// ---------------------------------------------------------------------------
#define QS 72
#define NT (S_LEN / 64)
#define AT_SMEM (384 * QS * 2)   // 55296 B

__device__ __forceinline__ void attn_stage_load(
    __half (*SN)[QS], const __half* Kh, const __half* Vh,
    size_t hbase, int kv0, int tid)
{
    #pragma unroll
    for (int i = 0; i < 2; i++) {
        int idx = tid + i * 256;
        int r = idx >> 3, c8 = (idx & 7) * 8;
        size_t src = hbase + (size_t)(kv0 + r) * DK + c8;
        cp16(smem_u32(&SN[r][c8]),      Kh + src);
        cp16(smem_u32(&SN[64 + r][c8]), Vh + src);
    }
    CP_COMMIT();
}

__global__ void __launch_bounds__(256, 2) attn_tc(
    const __half* __restrict__ Qh, const __half* __restrict__ Kh,
    const __half* __restrict__ Vh, __half* __restrict__ Ah)
{
    extern __shared__ __half sm[];
    __half (*ROWS)[QS] = (__half(*)[QS])sm;
    __half (*Qhs)[QS] = ROWS;                                  // rows 0..127
    __half (*stg[3])[QS] = { ROWS + 128, ROWS + 256, ROWS };   // S2 overlays Q

    const int tid = threadIdx.x, w = tid >> 5, lid = tid & 31;
    const int h = blockIdx.y, q0 = blockIdx.x * 128;
    const size_t hbase = (size_t)h * S_LEN * DK;

    #pragma unroll
    for (int i = 0; i < 2; i++) {               // Q: 512 uint4
        int idx = tid + i * 256;
        int r = idx >> 2, c8 = (idx & 3) * 16;
        size_t src = hbase + (size_t)(q0 + r) * DK + c8;
        *(uint4*)&Qhs[r][c8]     = *(const uint4*)(Qh + src);
        *(uint4*)&Qhs[r][c8 + 8] = *(const uint4*)(Qh + src + 8);
    }
    attn_stage_load(stg[0], Kh, Vh, hbase, 0,  tid);
    attn_stage_load(stg[1], Kh, Vh, hbase, 64, tid);
    __syncthreads();

    uint32_t qhf[4][4];
    #pragma unroll
    for (int ks = 0; ks < 4; ks++) {
        const int ac = 16 * ks + ((lid >> 4) << 3);
        ldsm4(qhf[ks], smem_u32(&Qhs[16 * w + (lid & 15)][ac]));
    }

    float O[8][4] = {};
    float m0r = -INFINITY, m1r = -INFINITY, l0r = 0.f, l1r = 0.f;

    for (int t = 0; t < NT; t++) {
        if (t == NT - 1) { CP_WAIT0(); } else { CP_WAIT1(); }
        __syncthreads();                // orders Q-hoist before S2 overwrite (t=0)
        if (t + 2 < NT)
            attn_stage_load(stg[(t + 2) % 3], Kh, Vh, hbase, (t + 2) * 64, tid);

        __half (*Khs)[QS] = stg[t % 3];
        __half (*Vhs)[QS] = Khs + 64;

        // S = Qh . Kh^T  -- 1 pass
        float s[8][4] = {};
        #pragma unroll
        for (int ks = 0; ks < 4; ks++) {
            const int ac = 16 * ks + ((lid >> 4) << 3);
            uint32_t bh[8][2], r4[4];
            #pragma unroll
            for (int jp = 0; jp < 4; jp++) {
                int rB = 16 * jp + (lid & 15);
                ldsm4(r4, smem_u32(&Khs[rB][ac]));
                bh[2*jp][0]=r4[0]; bh[2*jp][1]=r4[2]; bh[2*jp+1][0]=r4[1]; bh[2*jp+1][1]=r4[3];
            }
            #pragma unroll
            for (int j = 0; j < 8; j++) mma16816(s[j], qhf[ks], bh[j]);
        }

        // row max (fp32, log2 domain; scale folded into Q)
        float rm0 = -INFINITY, rm1 = -INFINITY;
        #pragma unroll
        for (int j = 0; j < 8; j++) {
            rm0 = fmaxf(rm0, fmaxf(s[j][0], s[j][1]));
            rm1 = fmaxf(rm1, fmaxf(s[j][2], s[j][3]));
        }
        rm0 = fmaxf(rm0, __shfl_xor_sync(~0u, rm0, 1)); rm0 = fmaxf(rm0, __shfl_xor_sync(~0u, rm0, 2));
        rm1 = fmaxf(rm1, __shfl_xor_sync(~0u, rm1, 1)); rm1 = fmaxf(rm1, __shfl_xor_sync(~0u, rm1, 2));
        float mn0 = fmaxf(m0r, rm0), mn1 = fmaxf(m1r, rm1);
        float c0 = ex2f(m0r - mn0), c1 = ex2f(m1r - mn1);
        m0r = mn0; m1r = mn1;

        // exp in fp16x2: P fragments produced directly.
        // ph[j2][0]/[2] hold row0 pairs, ph[j2][1]/[3] hold row1 pairs.
        uint32_t ph[4][4];
        #pragma unroll
        for (int j2 = 0; j2 < 4; j2++) {
            int t0 = 2 * j2, t1 = t0 + 1;
            __half2 a0 = __floats2half2_rn(s[t0][0] - mn0, s[t0][1] - mn0);
            __half2 a1 = __floats2half2_rn(s[t0][2] - mn1, s[t0][3] - mn1);
            __half2 a2 = __floats2half2_rn(s[t1][0] - mn0, s[t1][1] - mn0);
            __half2 a3 = __floats2half2_rn(s[t1][2] - mn1, s[t1][3] - mn1);
            __half2 p0 = h2exp2(a0), p1 = h2exp2(a1), p2 = h2exp2(a2), p3 = h2exp2(a3);
            ph[j2][0] = *(uint32_t*)&p0; ph[j2][1] = *(uint32_t*)&p1;
            ph[j2][2] = *(uint32_t*)&p2; ph[j2][3] = *(uint32_t*)&p3;
        }

        // row sums from the half2 fragments (hadd2 tree), then width-4 shfl
        __half2 t0h = __hadd2(__hadd2(*(__half2*)&ph[0][0], *(__half2*)&ph[0][2]),
                              __hadd2(*(__half2*)&ph[1][0], *(__half2*)&ph[1][2]));
        __half2 t1h = __hadd2(__hadd2(*(__half2*)&ph[2][0], *(__half2*)&ph[2][2]),
                              __hadd2(*(__half2*)&ph[3][0], *(__half2*)&ph[3][2]));
        t0h = __hadd2(t0h, t1h);
        float s0 = __low2float(t0h) + __high2float(t0h);
        __half2 u0h = __hadd2(__hadd2(*(__half2*)&ph[0][1], *(__half2*)&ph[0][3]),
                              __hadd2(*(__half2*)&ph[1][1], *(__half2*)&ph[1][3]));
        __half2 u1h = __hadd2(__hadd2(*(__half2*)&ph[2][1], *(__half2*)&ph[2][3]),
                              __hadd2(*(__half2*)&ph[3][1], *(__half2*)&ph[3][3]));
        u0h = __hadd2(u0h, u1h);
        float s1 = __low2float(u0h) + __high2float(u0h);
        s0 += __shfl_xor_sync(~0u, s0, 1); s0 += __shfl_xor_sync(~0u, s0, 2);
        s1 += __shfl_xor_sync(~0u, s1, 1); s1 += __shfl_xor_sync(~0u, s1, 2);
        l0r = l0r * c0 + s0; l1r = l1r * c1 + s1;
        #pragma unroll
        for (int j = 0; j < 8; j++) { O[j][0] *= c0; O[j][1] *= c0; O[j][2] *= c1; O[j][3] *= c1; }

        // O += Ph . Vh  -- 1 pass
        #pragma unroll
        for (int j2 = 0; j2 < 4; j2++) {
            uint32_t vh[8][2], r4[4];
            #pragma unroll
            for (int np = 0; np < 4; np++) {
                int rV = 16 * j2 + (lid & 15), cV = 16 * np + ((lid >> 4) << 3);
                ldsm4t(r4, smem_u32(&Vhs[rV][cV]));
                vh[2*np][0]=r4[0]; vh[2*np][1]=r4[1]; vh[2*np+1][0]=r4[2]; vh[2*np+1][1]=r4[3];
            }
            #pragma unroll
            for (int tt = 0; tt < 8; tt++) mma16816(O[tt], ph[j2], vh[tt]);
        }
    }

    float i0 = 1.f / l0r, i1 = 1.f / l1r;
    #pragma unroll
    for (int t = 0; t < 8; t++) {
        int c = h * DK + 8 * t + (lid & 3) * 2;
        int r0 = q0 + 16 * w + (lid >> 2);
        #pragma unroll
        for (int hrow = 0; hrow < 2; hrow++) {
            float f0 = O[t][2*hrow]   * (hrow ? i1 : i0);
            float f1 = O[t][2*hrow+1] * (hrow ? i1 : i0);
            size_t dst = (size_t)(r0 + hrow * 8) * DMODEL + c;
            *(uint32_t*)(Ah + dst) = pack_f16(f0, f1);
        }
    }
}

extern "C" void kernel_launch(void* const* d_in, const int* in_sizes, int n_in,
                              void* d_out, int out_size)
{
    const float* q  = (const float*)d_in[0];
    const float* k  = (const float*)d_in[1];
    const float* v  = (const float*)d_in[2];
    const float* Wq = (const float*)d_in[3];
    const float* bq = (const float*)d_in[4];
    const float* Wo = (const float*)d_in[5];
    const float* bo = (const float*)d_in[6];
    float* out = (float*)d_out;

    __half *xh, *wh, *wl, *qh, *kh, *vh, *ah;
    cudaGetSymbolAddress((void**)&xh, g_xh);
    cudaGetSymbolAddress((void**)&wh, g_wh); cudaGetSymbolAddress((void**)&wl, g_wl);
    cudaGetSymbolAddress((void**)&qh, g_qh);
    cudaGetSymbolAddress((void**)&kh, g_kh); cudaGetSymbolAddress((void**)&vh, g_vh);
    cudaGetSymbolAddress((void**)&ah, g_ah);

    cudaFuncSetAttribute(attn_tc,  cudaFuncAttributeMaxDynamicSharedMemorySize, AT_SMEM);
    cudaFuncSetAttribute(qkv_proj, cudaFuncAttributeMaxDynamicSharedMemorySize, QKV_SMEM);
    cudaFuncSetAttribute(out_proj, cudaFuncAttributeMaxDynamicSharedMemorySize, PROJ_SMEM);

    dim3 gc3(XN / 4 / 256, 1, 3);
    conv_hi3<<<gc3, 256>>>(q, k, v, xh, XN / 4);
    dim3 gc2(WN / 4 / 256, 1, 2);
    conv_hilo2<<<gc2, 256>>>(Wq, Wo, wh, wl, WN / 4);

    dim3 gqkv(DMODEL / 128, S_LEN / 128, 3);   // 6 x 32 x 3
    qkv_proj<<<gqkv, 256, QKV_SMEM>>>(xh, wh, bq, qh, kh, vh);

    dim3 gattn(S_LEN / 128, NH);               // 32 x 12
    attn_tc<<<gattn, 256, AT_SMEM>>>(qh, kh, vh, ah);

    dim3 gout(DMODEL / 128, S_LEN / 128);      // 6 x 32
    out_proj<<<gout, 256, PROJ_SMEM>>>(ah, wh + WN, wl + WN, bo, out);
}

// round 16
// speedup vs baseline: 1.0987x; 1.0987x over previous
#include <cuda_runtime.h>
#include <cuda_fp16.h>
#include <math.h>
#include <stdint.h>

#define S_LEN 4096
#define DMODEL 768
#define NH 12
#define DK 64
#define XN (S_LEN * DMODEL)
#define WN (DMODEL * DMODEL)

__device__ __half g_xh[3 * XN];
__device__ __half g_wh[2 * WN], g_wl[2 * WN];
__device__ __half g_qh[XN], g_kh[XN], g_vh[XN];
__device__ __half g_ah[XN];

__device__ __forceinline__ uint32_t smem_u32(const void* p) {
    uint32_t a;
    asm("{ .reg .u64 t; cvta.to.shared.u64 t, %1; cvt.u32.u64 %0, t; }" : "=r"(a) : "l"(p));
    return a;
}
__device__ __forceinline__ float ex2f(float x) {
    float r; asm("ex2.approx.ftz.f32 %0, %1;" : "=f"(r) : "f"(x)); return r;
}
__device__ __forceinline__ uint32_t pack_f16(float a, float b) {  // low=a, high=b
    __half2 h = __floats2half2_rn(a, b);
    return *(uint32_t*)&h;
}
__device__ __forceinline__ void ldsm4(uint32_t* r, uint32_t a) {
    asm volatile("ldmatrix.sync.aligned.m8n8.x4.shared.b16 {%0,%1,%2,%3}, [%4];"
                 : "=r"(r[0]), "=r"(r[1]), "=r"(r[2]), "=r"(r[3]) : "r"(a));
}
__device__ __forceinline__ void ldsm4t(uint32_t* r, uint32_t a) {
    asm volatile("ldmatrix.sync.aligned.m8n8.x4.trans.shared.b16 {%0,%1,%2,%3}, [%4];"
                 : "=r"(r[0]), "=r"(r[1]), "=r"(r[2]), "=r"(r[3]) : "r"(a));
}
__device__ __forceinline__ void mma16816(float* d, const uint32_t* a, const uint32_t* b) {
    asm volatile("mma.sync.aligned.m16n8k16.row.col.f32.f16.f16.f32 "
                 "{%0,%1,%2,%3}, {%4,%5,%6,%7}, {%8,%9}, {%0,%1,%2,%3};"
                 : "+f"(d[0]), "+f"(d[1]), "+f"(d[2]), "+f"(d[3])
                 : "r"(a[0]), "r"(a[1]), "r"(a[2]), "r"(a[3]), "r"(b[0]), "r"(b[1]));
}
__device__ __forceinline__ void cp16(uint32_t d, const void* s) {
    asm volatile("cp.async.cg.shared.global [%0], [%1], 16;" :: "r"(d), "l"(s));
}
#define CP_COMMIT() asm volatile("cp.async.commit_group;" ::: "memory")
#define CP_WAIT0()  asm volatile("cp.async.wait_group 0;" ::: "memory")
#define CP_WAIT1()  asm volatile("cp.async.wait_group 1;" ::: "memory")

// fp32 -> fp16 (hi only), 3 tensors via grid.z
__global__ void conv_hi3(const float* __restrict__ a, const float* __restrict__ b,
                         const float* __restrict__ c, __half* __restrict__ hi, int n4)
{
    int i = blockIdx.x * blockDim.x + threadIdx.x;
    if (i >= n4) return;
    const float* in = (blockIdx.z == 0) ? a : (blockIdx.z == 1) ? b : c;
    size_t off = (size_t)blockIdx.z * n4 + i;
    float4 v = ((const float4*)in)[i];
    ((__half2*)hi)[2 * off]     = __floats2half2_rn(v.x, v.y);
    ((__half2*)hi)[2 * off + 1] = __floats2half2_rn(v.z, v.w);
}
// fp32 -> fp16 hi+lo, 2 tensors via grid.z (weights; lo needed for Wo)
__global__ void conv_hilo2(const float* __restrict__ a, const float* __restrict__ b,
                           __half* __restrict__ hi, __half* __restrict__ lo, int n4)
{
    int i = blockIdx.x * blockDim.x + threadIdx.x;
    if (i >= n4) return;
    const float* in = (blockIdx.z == 0) ? a : b;
    size_t off = (size_t)blockIdx.z * n4 + i;
    float4 v = ((const float4*)in)[i];
    __half2 h01 = __floats2half2_rn(v.x, v.y), h23 = __floats2half2_rn(v.z, v.w);
    ((__half2*)hi)[2 * off] = h01; ((__half2*)hi)[2 * off + 1] = h23;
    ((__half2*)lo)[2 * off]     = __floats2half2_rn(v.x - __half2float(h01.x), v.y - __half2float(h01.y));
    ((__half2*)lo)[2 * off + 1] = __floats2half2_rn(v.z - __half2float(h23.x), v.w - __half2float(h23.y));
}

// ---------------------------------------------------------------------------
// QKV projection: SINGLE-pass fp16 GEMM, 2 matrices per stage [X | W].
// ---------------------------------------------------------------------------
#define PM 5120
#define P1STG (2 * PM)
#define QKV_SMEM (2 * P1STG * 2)   // 40960 B

__device__ __forceinline__ void qkv_stage_load(
    __half* st, const __half* X, const __half* W, int m0, int n0, int k0, int tid)
{
    #pragma unroll
    for (int i = 0; i < 2; i++) {
        int idx = tid + i * 256;
        int r = idx >> 2, c8 = (idx & 3) * 8;
        uint32_t base = smem_u32(st + r * 40 + c8);
        cp16(base,          X + (size_t)(m0 + r) * DMODEL + k0 + c8);
        cp16(base + PM * 2, W + (size_t)(n0 + r) * DMODEL + k0 + c8);
    }
    CP_COMMIT();
}

__global__ void __launch_bounds__(256, 2) qkv_proj(
    const __half* __restrict__ xh, const __half* __restrict__ Wh,
    const float* __restrict__ bias,
    __half* __restrict__ Qh, __half* __restrict__ Kh, __half* __restrict__ Vh)
{
    extern __shared__ __half sm[];
    const int tid = threadIdx.x, w = tid >> 5, lid = tid & 31;
    const int wm = w >> 1, wn = w & 1;
    const int m0 = blockIdx.y * 128, n0 = blockIdx.x * 128, z = blockIdx.z;
    const __half* X = xh + (size_t)z * XN;
    __half* Yh = (z == 0) ? Qh : (z == 1) ? Kh : Vh;
    const float sc = (z == 0) ? 0.18033688011112042f : 1.0f;  // 0.125*log2(e)

    float acc[2][8][4] = {};
    qkv_stage_load(sm, X, Wh, m0, n0, 0, tid);
    for (int t = 0; t < DMODEL / 32; t++) {
        CP_WAIT0();
        __syncthreads();
        if (t + 1 < DMODEL / 32)
            qkv_stage_load(sm + ((t + 1) & 1) * P1STG, X, Wh, m0, n0, (t + 1) * 32, tid);
        __half* P0 = sm + (t & 1) * P1STG;
        __half* P1 = P0 + PM;
        #pragma unroll
        for (int ks = 0; ks < 32; ks += 16) {
            const int ac = ks + ((lid >> 4) << 3);
            uint32_t a1[2][4], b1[8][2], r4[4];
            #pragma unroll
            for (int jp = 0; jp < 4; jp++) {
                int rB = 64 * wn + 16 * jp + (lid & 15);
                ldsm4(r4, smem_u32(P1 + rB * 40 + ac));
                b1[2*jp][0]=r4[0]; b1[2*jp][1]=r4[2]; b1[2*jp+1][0]=r4[1]; b1[2*jp+1][1]=r4[3];
            }
            #pragma unroll
            for (int i = 0; i < 2; i++) {
                int rA = 32 * wm + 16 * i + (lid & 15);
                ldsm4(a1[i], smem_u32(P0 + rA * 40 + ac));
            }
            #pragma unroll
            for (int i = 0; i < 2; i++)
                #pragma unroll
                for (int j = 0; j < 8; j++) mma16816(acc[i][j], a1[i], b1[j]);
        }
        __syncthreads();
    }

    #pragma unroll
    for (int i = 0; i < 2; i++) {
        int r = m0 + 32 * wm + 16 * i + (lid >> 2);
        #pragma unroll
        for (int j = 0; j < 8; j++) {
            int ng = n0 + 64 * wn + 8 * j + (lid & 3) * 2;
            float b0 = bias[ng], b1 = bias[ng + 1];
            int head = ng >> 6;
            #pragma unroll
            for (int hrow = 0; hrow < 2; hrow++) {
                int rr = r + hrow * 8;
                float f0 = (acc[i][j][2*hrow]   + b0) * sc;
                float f1 = (acc[i][j][2*hrow+1] + b1) * sc;
                size_t dst = ((size_t)head * S_LEN + rr) * DK + (ng & 63);
                *(uint32_t*)(Yh + dst) = pack_f16(f0, f1);
            }
        }
    }
}

// ---------------------------------------------------------------------------
// Output projection: 2-pass Ah·(Wh+Wl), 3 matrices per stage.
// ---------------------------------------------------------------------------
#define PSTG (3 * PM)
#define PROJ_SMEM (2 * PSTG * 2)   // 61440 B

__device__ __forceinline__ void out_stage_load(
    __half* st, const __half* A, const __half* Wh, const __half* Wl,
    int m0, int n0, int k0, int tid)
{
    #pragma unroll
    for (int i = 0; i < 2; i++) {
        int idx = tid + i * 256;
        int r = idx >> 2, c8 = (idx & 3) * 8;
        size_t ms = (size_t)(m0 + r) * DMODEL + k0 + c8;
        size_t ns = (size_t)(n0 + r) * DMODEL + k0 + c8;
        uint32_t base = smem_u32(st + r * 40 + c8);
        cp16(base,              A + ms);
        cp16(base + PM * 2,     Wh + ns);
        cp16(base + 2 * PM * 2, Wl + ns);
    }
    CP_COMMIT();
}

__global__ void __launch_bounds__(256, 2) out_proj(
    const __half* __restrict__ Ah,
    const __half* __restrict__ Wh, const __half* __restrict__ Wl,
    const float* __restrict__ bias, float* __restrict__ Yf)
{
    extern __shared__ __half sm[];
    const int tid = threadIdx.x, w = tid >> 5, lid = tid & 31;
    const int wm = w >> 1, wn = w & 1;
    const int m0 = blockIdx.y * 128, n0 = blockIdx.x * 128;

    float acc[2][8][4] = {};
    out_stage_load(sm, Ah, Wh, Wl, m0, n0, 0, tid);
    for (int t = 0; t < DMODEL / 32; t++) {
        CP_WAIT0();
        __syncthreads();
        if (t + 1 < DMODEL / 32)
            out_stage_load(sm + ((t + 1) & 1) * PSTG, Ah, Wh, Wl, m0, n0, (t + 1) * 32, tid);
        __half* P0 = sm + (t & 1) * PSTG;
        __half* P1 = P0 + PM;
        __half* P2 = P0 + 2 * PM;
        #pragma unroll
        for (int ks = 0; ks < 32; ks += 16) {
            const int ac = ks + ((lid >> 4) << 3);
            uint32_t a1[2][4], b1[8][2], b2[8][2], r4[4];
            #pragma unroll
            for (int jp = 0; jp < 4; jp++) {
                int rB = 64 * wn + 16 * jp + (lid & 15);
                ldsm4(r4, smem_u32(P1 + rB * 40 + ac));
                b1[2*jp][0]=r4[0]; b1[2*jp][1]=r4[2]; b1[2*jp+1][0]=r4[1]; b1[2*jp+1][1]=r4[3];
                ldsm4(r4, smem_u32(P2 + rB * 40 + ac));
                b2[2*jp][0]=r4[0]; b2[2*jp][1]=r4[2]; b2[2*jp+1][0]=r4[1]; b2[2*jp+1][1]=r4[3];
            }
            #pragma unroll
            for (int i = 0; i < 2; i++) {
                int rA = 32 * wm + 16 * i + (lid & 15);
                ldsm4(a1[i], smem_u32(P0 + rA * 40 + ac));
            }
            #pragma unroll
            for (int i = 0; i < 2; i++) {
                #pragma unroll
                for (int j = 0; j < 8; j++) mma16816(acc[i][j], a1[i], b1[j]);
                #pragma unroll
                for (int j = 0; j < 8; j++) mma16816(acc[i][j], a1[i], b2[j]);
            }
        }
        __syncthreads();
    }

    #pragma unroll
    for (int i = 0; i < 2; i++) {
        int r = m0 + 32 * wm + 16 * i + (lid >> 2);
        #pragma unroll
        for (int j = 0; j < 8; j++) {
            int ng = n0 + 64 * wn + 8 * j + (lid & 3) * 2;
            float b0 = bias[ng], b1 = bias[ng + 1];
            #pragma unroll
            for (int hrow = 0; hrow < 2; hrow++) {
                int rr = r + hrow * 8;
                Yf[(size_t)rr * DMODEL + ng]     = acc[i][j][2*hrow]   + b0;
                Yf[(size_t)rr * DMODEL + ng + 1] = acc[i][j][2*hrow+1] + b1;
            }
        }
    }
}

// ---------------------------------------------------------------------------
// Flash attention: CTA=(head, 128 q rows), 8 warps, Bc=64, fp16.
// S = Qh·Kh (1 pass); fp32 softmax (R14 path); O = Ph·Vh (1 pass).
// 3-stage pipeline with STATIC register rotation of stage bases and fully
// precomputed per-thread cp.async / ldsm offsets (immediate addressing).
// Stage = [K 64 rows | V 64 rows]; stage C overlays the dead Q rows.
// ---------------------------------------------------------------------------
#define QS 72
#define NT (S_LEN / 64)
#define AT_SMEM (384 * QS * 2)   // 55296 B
#define TILE_ELEMS (64 * DK)     // global elements per K (or V) tile

__device__ __forceinline__ void attn_prefetch(
    uint32_t sb, const __half* kp, const __half* vp,
    uint32_t lk0, uint32_t lk1, uint32_t g0, uint32_t g1)
{
    cp16(sb + lk0,                kp + g0);
    cp16(sb + lk1,                kp + g1);
    cp16(sb + lk0 + 64 * QS * 2,  vp + g0);
    cp16(sb + lk1 + 64 * QS * 2,  vp + g1);
    CP_COMMIT();
}

__global__ void __launch_bounds__(256, 2) attn_tc(
    const __half* __restrict__ Qh, const __half* __restrict__ Kh,
    const __half* __restrict__ Vh, __half* __restrict__ Ah)
{
    extern __shared__ __half sm[];
    __half (*ROWS)[QS] = (__half(*)[QS])sm;
    __half (*Qhs)[QS] = ROWS;                    // rows 0..127 (dead after hoist)

    const int tid = threadIdx.x, w = tid >> 5, lid = tid & 31;
    const int h = blockIdx.y, q0 = blockIdx.x * 128;
    const size_t hbase = (size_t)h * S_LEN * DK;

    // ---- precomputed addressing ----
    // cp.async: per-thread smem byte offsets within a stage + global elem offsets
    const uint32_t lk0 = (uint32_t)(((tid) >> 3) * QS + (tid & 7) * 8) * 2;
    const uint32_t lk1 = (uint32_t)(((tid + 256) >> 3) * QS + (tid & 7) * 8) * 2;
    const uint32_t g0  = (uint32_t)(((tid) >> 3) * DK + (tid & 7) * 8);
    const uint32_t g1  = (uint32_t)(((tid + 256) >> 3) * DK + (tid & 7) * 8);
    // stage bases (bytes, smem)
    uint32_t sbA = smem_u32(&ROWS[128][0]);
    uint32_t sbB = smem_u32(&ROWS[256][0]);
    uint32_t sbC = smem_u32(&ROWS[0][0]);        // overlays Q
    // ldsm per-lane base offset within a stage (bytes)
    const uint32_t lmb = (uint32_t)((lid & 15) * QS + ((lid >> 4) << 3)) * 2;

    // ---- Q load + fragment hoist ----
    #pragma unroll
    for (int i = 0; i < 2; i++) {
        int idx = tid + i * 256;
        int r = idx >> 2, c8 = (idx & 3) * 16;
        size_t src = hbase + (size_t)(q0 + r) * DK + c8;
        *(uint4*)&Qhs[r][c8]     = *(const uint4*)(Qh + src);
        *(uint4*)&Qhs[r][c8 + 8] = *(const uint4*)(Qh + src + 8);
    }
    const __half* kp = Kh + hbase;
    const __half* vp = Vh + hbase;
    attn_prefetch(sbA, kp, vp, lk0, lk1, g0, g1);
    attn_prefetch(sbB, kp + TILE_ELEMS, vp + TILE_ELEMS, lk0, lk1, g0, g1);
    const __half* kpn = kp + 2 * TILE_ELEMS;     // next-to-prefetch pointers
    const __half* vpn = vp + 2 * TILE_ELEMS;
    __syncthreads();

    uint32_t qhf[4][4];
    #pragma unroll
    for (int ks = 0; ks < 4; ks++) {
        const int ac = 16 * ks + ((lid >> 4) << 3);
        ldsm4(qhf[ks], smem_u32(&Qhs[16 * w + (lid & 15)][ac]));
    }

    float O[8][4] = {};
    float m0r = -INFINITY, m1r = -INFINITY, l0r = 0.f, l1r = 0.f;
    uint32_t cur = sbA, nxt = sbB, nn = sbC;

    for (int t = 0; t < NT; t++) {
        if (t == NT - 1) { CP_WAIT0(); } else { CP_WAIT1(); }
        __syncthreads();                // orders Q-hoist before stage-C overwrite (t=0)
        if (t + 2 < NT) {
            attn_prefetch(nn, kpn, vpn, lk0, lk1, g0, g1);
            kpn += TILE_ELEMS; vpn += TILE_ELEMS;
        }

        const uint32_t kbase = cur + lmb;                 // K ldsm lane base
        const uint32_t vbase = cur + 64 * QS * 2 + lmb;   // V ldsm lane base

        // S = Qh . Kh^T  -- 1 pass (addresses: base + immediates)
        float s[8][4] = {};
        #pragma unroll
        for (int ks = 0; ks < 4; ks++) {
            uint32_t bh[8][2], r4[4];
            #pragma unroll
            for (int jp = 0; jp < 4; jp++) {
                ldsm4(r4, kbase + (uint32_t)(jp * 16 * QS + ks * 16) * 2);
                bh[2*jp][0]=r4[0]; bh[2*jp][1]=r4[2]; bh[2*jp+1][0]=r4[1]; bh[2*jp+1][1]=r4[3];
            }
            #pragma unroll
            for (int j = 0; j < 8; j++) mma16816(s[j], qhf[ks], bh[j]);
        }

        // online softmax (fp32, log2 domain; scale folded into Q)
        float rm0 = -INFINITY, rm1 = -INFINITY;
        #pragma unroll
        for (int j = 0; j < 8; j++) {
            rm0 = fmaxf(rm0, fmaxf(s[j][0], s[j][1]));
            rm1 = fmaxf(rm1, fmaxf(s[j][2], s[j][3]));
        }
        rm0 = fmaxf(rm0, __shfl_xor_sync(~0u, rm0, 1)); rm0 = fmaxf(rm0, __shfl_xor_sync(~0u, rm0, 2));
        rm1 = fmaxf(rm1, __shfl_xor_sync(~0u, rm1, 1)); rm1 = fmaxf(rm1, __shfl_xor_sync(~0u, rm1, 2));
        float mn0 = fmaxf(m0r, rm0), mn1 = fmaxf(m1r, rm1);
        float c0 = ex2f(m0r - mn0), c1 = ex2f(m1r - mn1);
        m0r = mn0; m1r = mn1;
        float s0 = 0.f, s1 = 0.f;
        #pragma unroll
        for (int j = 0; j < 8; j++) {
            s[j][0] = ex2f(s[j][0] - mn0); s[j][1] = ex2f(s[j][1] - mn0);
            s[j][2] = ex2f(s[j][2] - mn1); s[j][3] = ex2f(s[j][3] - mn1);
            s0 += s[j][0] + s[j][1]; s1 += s[j][2] + s[j][3];
        }
        s0 += __shfl_xor_sync(~0u, s0, 1); s0 += __shfl_xor_sync(~0u, s0, 2);
        s1 += __shfl_xor_sync(~0u, s1, 1); s1 += __shfl_xor_sync(~0u, s1, 2);
        l0r = l0r * c0 + s0; l1r = l1r * c1 + s1;
        #pragma unroll
        for (int j = 0; j < 8; j++) { O[j][0] *= c0; O[j][1] *= c0; O[j][2] *= c1; O[j][3] *= c1; }

        // P -> fp16 A-fragments
        uint32_t ph[4][4];
        #pragma unroll
        for (int j2 = 0; j2 < 4; j2++) {
            int t0 = 2 * j2, t1 = t0 + 1;
            ph[j2][0] = pack_f16(s[t0][0], s[t0][1]); ph[j2][1] = pack_f16(s[t0][2], s[t0][3]);
            ph[j2][2] = pack_f16(s[t1][0], s[t1][1]); ph[j2][3] = pack_f16(s[t1][2], s[t1][3]);
        }

        // O += Ph . Vh  -- 1 pass
        #pragma unroll
        for (int j2 = 0; j2 < 4; j2++) {
            uint32_t vh[8][2], r4[4];
            #pragma unroll
            for (int np = 0; np < 4; np++) {
                ldsm4t(r4, vbase + (uint32_t)(j2 * 16 * QS + np * 16) * 2);
                vh[2*np][0]=r4[0]; vh[2*np][1]=r4[1]; vh[2*np+1][0]=r4[2]; vh[2*np+1][1]=r4[3];
            }
            #pragma unroll
            for (int tt = 0; tt < 8; tt++) mma16816(O[tt], ph[j2], vh[tt]);
        }

        // static stage rotation (register moves only)
        uint32_t tmp = cur; cur = nxt; nxt = nn; nn = tmp;
    }

    float i0 = 1.f / l0r, i1 = 1.f / l1r;
    #pragma unroll
    for (int t = 0; t < 8; t++) {
        int c = h * DK + 8 * t + (lid & 3) * 2;
        int r0 = q0 + 16 * w + (lid >> 2);
        #pragma unroll
        for (int hrow = 0; hrow < 2; hrow++) {
            float f0 = O[t][2*hrow]   * (hrow ? i1 : i0);
            float f1 = O[t][2*hrow+1] * (hrow ? i1 : i0);
            size_t dst = (size_t)(r0 + hrow * 8) * DMODEL + c;
            *(uint32_t*)(Ah + dst) = pack_f16(f0, f1);
        }
    }
}

extern "C" void kernel_launch(void* const* d_in, const int* in_sizes, int n_in,
                              void* d_out, int out_size)
{
    const float* q  = (const float*)d_in[0];
    const float* k  = (const float*)d_in[1];
    const float* v  = (const float*)d_in[2];
    const float* Wq = (const float*)d_in[3];
    const float* bq = (const float*)d_in[4];
    const float* Wo = (const float*)d_in[5];
    const float* bo = (const float*)d_in[6];
    float* out = (float*)d_out;

    __half *xh, *wh, *wl, *qh, *kh, *vh, *ah;
    cudaGetSymbolAddress((void**)&xh, g_xh);
    cudaGetSymbolAddress((void**)&wh, g_wh); cudaGetSymbolAddress((void**)&wl, g_wl);
    cudaGetSymbolAddress((void**)&qh, g_qh);
    cudaGetSymbolAddress((void**)&kh, g_kh); cudaGetSymbolAddress((void**)&vh, g_vh);
    cudaGetSymbolAddress((void**)&ah, g_ah);

    cudaFuncSetAttribute(attn_tc,  cudaFuncAttributeMaxDynamicSharedMemorySize, AT_SMEM);
    cudaFuncSetAttribute(qkv_proj, cudaFuncAttributeMaxDynamicSharedMemorySize, QKV_SMEM);
    cudaFuncSetAttribute(out_proj, cudaFuncAttributeMaxDynamicSharedMemorySize, PROJ_SMEM);

    dim3 gc3(XN / 4 / 256, 1, 3);
    conv_hi3<<<gc3, 256>>>(q, k, v, xh, XN / 4);
    dim3 gc2(WN / 4 / 256, 1, 2);
    conv_hilo2<<<gc2, 256>>>(Wq, Wo, wh, wl, WN / 4);

    dim3 gqkv(DMODEL / 128, S_LEN / 128, 3);   // 6 x 32 x 3
    qkv_proj<<<gqkv, 256, QKV_SMEM>>>(xh, wh, bq, qh, kh, vh);

    dim3 gattn(S_LEN / 128, NH);               // 32 x 12
    attn_tc<<<gattn, 256, AT_SMEM>>>(qh, kh, vh, ah);

    dim3 gout(DMODEL / 128, S_LEN / 128);      // 6 x 32
    out_proj<<<gout, 256, PROJ_SMEM>>>(ah, wh + WN, wl + WN, bo, out);
}

// round 17
// speedup vs baseline: 1.0988x; 1.0001x over previous
#include <cuda_runtime.h>
#include <cuda_fp16.h>
#include <math.h>
#include <stdint.h>

#define S_LEN 4096
#define DMODEL 768
#define NH 12
#define DK 64
#define XN (S_LEN * DMODEL)
#define WN (DMODEL * DMODEL)

__device__ __half g_xh[3 * XN];
__device__ __half g_wh[2 * WN], g_wl[2 * WN];
__device__ __half g_qh[XN], g_kh[XN], g_vh[XN];
__device__ __half g_ah[XN];
__device__ __half g_p0[XN], g_p1[XN];                 // split-KV partial O (normalized)
__device__ float  g_pm0[NH * S_LEN], g_pl0[NH * S_LEN];
__device__ float  g_pm1[NH * S_LEN], g_pl1[NH * S_LEN];

__device__ __forceinline__ uint32_t smem_u32(const void* p) {
    uint32_t a;
    asm("{ .reg .u64 t; cvta.to.shared.u64 t, %1; cvt.u32.u64 %0, t; }" : "=r"(a) : "l"(p));
    return a;
}
__device__ __forceinline__ float ex2f(float x) {
    float r; asm("ex2.approx.ftz.f32 %0, %1;" : "=f"(r) : "f"(x)); return r;
}
__device__ __forceinline__ uint32_t pack_f16(float a, float b) {  // low=a, high=b
    __half2 h = __floats2half2_rn(a, b);
    return *(uint32_t*)&h;
}
__device__ __forceinline__ void ldsm4(uint32_t* r, uint32_t a) {
    asm volatile("ldmatrix.sync.aligned.m8n8.x4.shared.b16 {%0,%1,%2,%3}, [%4];"
                 : "=r"(r[0]), "=r"(r[1]), "=r"(r[2]), "=r"(r[3]) : "r"(a));
}
__device__ __forceinline__ void ldsm4t(uint32_t* r, uint32_t a) {
    asm volatile("ldmatrix.sync.aligned.m8n8.x4.trans.shared.b16 {%0,%1,%2,%3}, [%4];"
                 : "=r"(r[0]), "=r"(r[1]), "=r"(r[2]), "=r"(r[3]) : "r"(a));
}
__device__ __forceinline__ void mma16816(float* d, const uint32_t* a, const uint32_t* b) {
    asm volatile("mma.sync.aligned.m16n8k16.row.col.f32.f16.f16.f32 "
                 "{%0,%1,%2,%3}, {%4,%5,%6,%7}, {%8,%9}, {%0,%1,%2,%3};"
                 : "+f"(d[0]), "+f"(d[1]), "+f"(d[2]), "+f"(d[3])
                 : "r"(a[0]), "r"(a[1]), "r"(a[2]), "r"(a[3]), "r"(b[0]), "r"(b[1]));
}
__device__ __forceinline__ void cp16(uint32_t d, const void* s) {
    asm volatile("cp.async.cg.shared.global [%0], [%1], 16;" :: "r"(d), "l"(s));
}
#define CP_COMMIT() asm volatile("cp.async.commit_group;" ::: "memory")
#define CP_WAIT0()  asm volatile("cp.async.wait_group 0;" ::: "memory")
#define CP_WAIT1()  asm volatile("cp.async.wait_group 1;" ::: "memory")

__global__ void conv_hi3(const float* __restrict__ a, const float* __restrict__ b,
                         const float* __restrict__ c, __half* __restrict__ hi, int n4)
{
    int i = blockIdx.x * blockDim.x + threadIdx.x;
    if (i >= n4) return;
    const float* in = (blockIdx.z == 0) ? a : (blockIdx.z == 1) ? b : c;
    size_t off = (size_t)blockIdx.z * n4 + i;
    float4 v = ((const float4*)in)[i];
    ((__half2*)hi)[2 * off]     = __floats2half2_rn(v.x, v.y);
    ((__half2*)hi)[2 * off + 1] = __floats2half2_rn(v.z, v.w);
}
__global__ void conv_hilo2(const float* __restrict__ a, const float* __restrict__ b,
                           __half* __restrict__ hi, __half* __restrict__ lo, int n4)
{
    int i = blockIdx.x * blockDim.x + threadIdx.x;
    if (i >= n4) return;
    const float* in = (blockIdx.z == 0) ? a : b;
    size_t off = (size_t)blockIdx.z * n4 + i;
    float4 v = ((const float4*)in)[i];
    __half2 h01 = __floats2half2_rn(v.x, v.y), h23 = __floats2half2_rn(v.z, v.w);
    ((__half2*)hi)[2 * off] = h01; ((__half2*)hi)[2 * off + 1] = h23;
    ((__half2*)lo)[2 * off]     = __floats2half2_rn(v.x - __half2float(h01.x), v.y - __half2float(h01.y));
    ((__half2*)lo)[2 * off + 1] = __floats2half2_rn(v.z - __half2float(h23.x), v.w - __half2float(h23.y));
}

// ---------------------------------------------------------------------------
// QKV projection: SINGLE-pass fp16 GEMM (unchanged from R16).
// ---------------------------------------------------------------------------
#define PM 5120
#define P1STG (2 * PM)
#define QKV_SMEM (2 * P1STG * 2)

__device__ __forceinline__ void qkv_stage_load(
    __half* st, const __half* X, const __half* W, int m0, int n0, int k0, int tid)
{
    #pragma unroll
    for (int i = 0; i < 2; i++) {
        int idx = tid + i * 256;
        int r = idx >> 2, c8 = (idx & 3) * 8;
        uint32_t base = smem_u32(st + r * 40 + c8);
        cp16(base,          X + (size_t)(m0 + r) * DMODEL + k0 + c8);
        cp16(base + PM * 2, W + (size_t)(n0 + r) * DMODEL + k0 + c8);
    }
    CP_COMMIT();
}

__global__ void __launch_bounds__(256, 2) qkv_proj(
    const __half* __restrict__ xh, const __half* __restrict__ Wh,
    const float* __restrict__ bias,
    __half* __restrict__ Qh, __half* __restrict__ Kh, __half* __restrict__ Vh)
{
    extern __shared__ __half sm[];
    const int tid = threadIdx.x, w = tid >> 5, lid = tid & 31;
    const int wm = w >> 1, wn = w & 1;
    const int m0 = blockIdx.y * 128, n0 = blockIdx.x * 128, z = blockIdx.z;
    const __half* X = xh + (size_t)z * XN;
    __half* Yh = (z == 0) ? Qh : (z == 1) ? Kh : Vh;
    const float sc = (z == 0) ? 0.18033688011112042f : 1.0f;  // 0.125*log2(e)

    float acc[2][8][4] = {};
    qkv_stage_load(sm, X, Wh, m0, n0, 0, tid);
    for (int t = 0; t < DMODEL / 32; t++) {
        CP_WAIT0();
        __syncthreads();
        if (t + 1 < DMODEL / 32)
            qkv_stage_load(sm + ((t + 1) & 1) * P1STG, X, Wh, m0, n0, (t + 1) * 32, tid);
        __half* P0 = sm + (t & 1) * P1STG;
        __half* P1 = P0 + PM;
        #pragma unroll
        for (int ks = 0; ks < 32; ks += 16) {
            const int ac = ks + ((lid >> 4) << 3);
            uint32_t a1[2][4], b1[8][2], r4[4];
            #pragma unroll
            for (int jp = 0; jp < 4; jp++) {
                int rB = 64 * wn + 16 * jp + (lid & 15);
                ldsm4(r4, smem_u32(P1 + rB * 40 + ac));
                b1[2*jp][0]=r4[0]; b1[2*jp][1]=r4[2]; b1[2*jp+1][0]=r4[1]; b1[2*jp+1][1]=r4[3];
            }
            #pragma unroll
            for (int i = 0; i < 2; i++) {
                int rA = 32 * wm + 16 * i + (lid & 15);
                ldsm4(a1[i], smem_u32(P0 + rA * 40 + ac));
            }
            #pragma unroll
            for (int i = 0; i < 2; i++)
                #pragma unroll
                for (int j = 0; j < 8; j++) mma16816(acc[i][j], a1[i], b1[j]);
        }
        __syncthreads();
    }

    #pragma unroll
    for (int i = 0; i < 2; i++) {
        int r = m0 + 32 * wm + 16 * i + (lid >> 2);
        #pragma unroll
        for (int j = 0; j < 8; j++) {
            int ng = n0 + 64 * wn + 8 * j + (lid & 3) * 2;
            float b0 = bias[ng], b1 = bias[ng + 1];
            int head = ng >> 6;
            #pragma unroll
            for (int hrow = 0; hrow < 2; hrow++) {
                int rr = r + hrow * 8;
                float f0 = (acc[i][j][2*hrow]   + b0) * sc;
                float f1 = (acc[i][j][2*hrow+1] + b1) * sc;
                size_t dst = ((size_t)head * S_LEN + rr) * DK + (ng & 63);
                *(uint32_t*)(Yh + dst) = pack_f16(f0, f1);
            }
        }
    }
}

// ---------------------------------------------------------------------------
// Output projection: 2-pass Ah·(Wh+Wl) (unchanged from R16).
// ---------------------------------------------------------------------------
#define PSTG (3 * PM)
#define PROJ_SMEM (2 * PSTG * 2)

__device__ __forceinline__ void out_stage_load(
    __half* st, const __half* A, const __half* Wh, const __half* Wl,
    int m0, int n0, int k0, int tid)
{
    #pragma unroll
    for (int i = 0; i < 2; i++) {
        int idx = tid + i * 256;
        int r = idx >> 2, c8 = (idx & 3) * 8;
        size_t ms = (size_t)(m0 + r) * DMODEL + k0 + c8;
        size_t ns = (size_t)(n0 + r) * DMODEL + k0 + c8;
        uint32_t base = smem_u32(st + r * 40 + c8);
        cp16(base,              A + ms);
        cp16(base + PM * 2,     Wh + ns);
        cp16(base + 2 * PM * 2, Wl + ns);
    }
    CP_COMMIT();
}

__global__ void __launch_bounds__(256, 2) out_proj(
    const __half* __restrict__ Ah,
    const __half* __restrict__ Wh, const __half* __restrict__ Wl,
    const float* __restrict__ bias, float* __restrict__ Yf)
{
    extern __shared__ __half sm[];
    const int tid = threadIdx.x, w = tid >> 5, lid = tid & 31;
    const int wm = w >> 1, wn = w & 1;
    const int m0 = blockIdx.y * 128, n0 = blockIdx.x * 128;

    float acc[2][8][4] = {};
    out_stage_load(sm, Ah, Wh, Wl, m0, n0, 0, tid);
    for (int t = 0; t < DMODEL / 32; t++) {
        CP_WAIT0();
        __syncthreads();
        if (t + 1 < DMODEL / 32)
            out_stage_load(sm + ((t + 1) & 1) * PSTG, Ah, Wh, Wl, m0, n0, (t + 1) * 32, tid);
        __half* P0 = sm + (t & 1) * PSTG;
        __half* P1 = P0 + PM;
        __half* P2 = P0 + 2 * PM;
        #pragma unroll
        for (int ks = 0; ks < 32; ks += 16) {
            const int ac = ks + ((lid >> 4) << 3);
            uint32_t a1[2][4], b1[8][2], b2[8][2], r4[4];
            #pragma unroll
            for (int jp = 0; jp < 4; jp++) {
                int rB = 64 * wn + 16 * jp + (lid & 15);
                ldsm4(r4, smem_u32(P1 + rB * 40 + ac));
                b1[2*jp][0]=r4[0]; b1[2*jp][1]=r4[2]; b1[2*jp+1][0]=r4[1]; b1[2*jp+1][1]=r4[3];
                ldsm4(r4, smem_u32(P2 + rB * 40 + ac));
                b2[2*jp][0]=r4[0]; b2[2*jp][1]=r4[2]; b2[2*jp+1][0]=r4[1]; b2[2*jp+1][1]=r4[3];
            }
            #pragma unroll
            for (int i = 0; i < 2; i++) {
                int rA = 32 * wm + 16 * i + (lid & 15);
                ldsm4(a1[i], smem_u32(P0 + rA * 40 + ac));
            }
            #pragma unroll
            for (int i = 0; i < 2; i++) {
                #pragma unroll
                for (int j = 0; j < 8; j++) mma16816(acc[i][j], a1[i], b1[j]);
                #pragma unroll
                for (int j = 0; j < 8; j++) mma16816(acc[i][j], a1[i], b2[j]);
            }
        }
        __syncthreads();
    }

    #pragma unroll
    for (int i = 0; i < 2; i++) {
        int r = m0 + 32 * wm + 16 * i + (lid >> 2);
        #pragma unroll
        for (int j = 0; j < 8; j++) {
            int ng = n0 + 64 * wn + 8 * j + (lid & 3) * 2;
            float b0 = bias[ng], b1 = bias[ng + 1];
            #pragma unroll
            for (int hrow = 0; hrow < 2; hrow++) {
                int rr = r + hrow * 8;
                Yf[(size_t)rr * DMODEL + ng]     = acc[i][j][2*hrow]   + b0;
                Yf[(size_t)rr * DMODEL + ng + 1] = acc[i][j][2*hrow+1] + b1;
            }
        }
    }
}

// ---------------------------------------------------------------------------
// Flash attention, SPLIT-KV 2-way: CTA=(head, qtile, kvhalf). Each job scans
// 2048 KV rows (32 tiles). Writes normalized partial O (fp16) + per-row (m,l).
// R16 addressing scheme (static stage rotation, precomputed offsets).
// ---------------------------------------------------------------------------
#define QS 72
#define NTH (S_LEN / 2 / 64)      // 32 tiles per half
#define AT_SMEM (384 * QS * 2)
#define TILE_ELEMS (64 * DK)

__device__ __forceinline__ void attn_prefetch(
    uint32_t sb, const __half* kp, const __half* vp,
    uint32_t lk0, uint32_t lk1, uint32_t g0, uint32_t g1)
{
    cp16(sb + lk0,                kp + g0);
    cp16(sb + lk1,                kp + g1);
    cp16(sb + lk0 + 64 * QS * 2,  vp + g0);
    cp16(sb + lk1 + 64 * QS * 2,  vp + g1);
    CP_COMMIT();
}

__global__ void __launch_bounds__(256, 2) attn_tc(
    const __half* __restrict__ Qh, const __half* __restrict__ Kh,
    const __half* __restrict__ Vh,
    __half* __restrict__ P0o, __half* __restrict__ P1o,
    float* __restrict__ pm0, float* __restrict__ pl0,
    float* __restrict__ pm1, float* __restrict__ pl1)
{
    extern __shared__ __half sm[];
    __half (*ROWS)[QS] = (__half(*)[QS])sm;
    __half (*Qhs)[QS] = ROWS;

    const int tid = threadIdx.x, w = tid >> 5, lid = tid & 31;
    const int h = blockIdx.y;
    const int qi = blockIdx.x >> 1, half = blockIdx.x & 1;
    const int q0 = qi * 128;
    const size_t hbase = (size_t)h * S_LEN * DK;
    const size_t kvoff = hbase + (size_t)half * (S_LEN / 2) * DK;
    __half* Oo = half ? P1o : P0o;
    float*  pm = half ? pm1 : pm0;
    float*  pl = half ? pl1 : pl0;

    const uint32_t lk0 = (uint32_t)(((tid) >> 3) * QS + (tid & 7) * 8) * 2;
    const uint32_t lk1 = (uint32_t)(((tid + 256) >> 3) * QS + (tid & 7) * 8) * 2;
    const uint32_t g0  = (uint32_t)(((tid) >> 3) * DK + (tid & 7) * 8);
    const uint32_t g1  = (uint32_t)(((tid + 256) >> 3) * DK + (tid & 7) * 8);
    uint32_t sbA = smem_u32(&ROWS[128][0]);
    uint32_t sbB = smem_u32(&ROWS[256][0]);
    uint32_t sbC = smem_u32(&ROWS[0][0]);
    const uint32_t lmb = (uint32_t)((lid & 15) * QS + ((lid >> 4) << 3)) * 2;

    #pragma unroll
    for (int i = 0; i < 2; i++) {
        int idx = tid + i * 256;
        int r = idx >> 2, c8 = (idx & 3) * 16;
        size_t src = hbase + (size_t)(q0 + r) * DK + c8;
        *(uint4*)&Qhs[r][c8]     = *(const uint4*)(Qh + src);
        *(uint4*)&Qhs[r][c8 + 8] = *(const uint4*)(Qh + src + 8);
    }
    const __half* kp = Kh + kvoff;
    const __half* vp = Vh + kvoff;
    attn_prefetch(sbA, kp, vp, lk0, lk1, g0, g1);
    attn_prefetch(sbB, kp + TILE_ELEMS, vp + TILE_ELEMS, lk0, lk1, g0, g1);
    const __half* kpn = kp + 2 * TILE_ELEMS;
    const __half* vpn = vp + 2 * TILE_ELEMS;
    __syncthreads();

    uint32_t qhf[4][4];
    #pragma unroll
    for (int ks = 0; ks < 4; ks++) {
        const int ac = 16 * ks + ((lid >> 4) << 3);
        ldsm4(qhf[ks], smem_u32(&Qhs[16 * w + (lid & 15)][ac]));
    }

    float O[8][4] = {};
    float m0r = -INFINITY, m1r = -INFINITY, l0r = 0.f, l1r = 0.f;
    uint32_t cur = sbA, nxt = sbB, nn = sbC;

    for (int t = 0; t < NTH; t++) {
        if (t == NTH - 1) { CP_WAIT0(); } else { CP_WAIT1(); }
        __syncthreads();
        if (t + 2 < NTH) {
            attn_prefetch(nn, kpn, vpn, lk0, lk1, g0, g1);
            kpn += TILE_ELEMS; vpn += TILE_ELEMS;
        }

        const uint32_t kbase = cur + lmb;
        const uint32_t vbase = cur + 64 * QS * 2 + lmb;

        float s[8][4] = {};
        #pragma unroll
        for (int ks = 0; ks < 4; ks++) {
            uint32_t bh[8][2], r4[4];
            #pragma unroll
            for (int jp = 0; jp < 4; jp++) {
                ldsm4(r4, kbase + (uint32_t)(jp * 16 * QS + ks * 16) * 2);
                bh[2*jp][0]=r4[0]; bh[2*jp][1]=r4[2]; bh[2*jp+1][0]=r4[1]; bh[2*jp+1][1]=r4[3];
            }
            #pragma unroll
            for (int j = 0; j < 8; j++) mma16816(s[j], qhf[ks], bh[j]);
        }

        float rm0 = -INFINITY, rm1 = -INFINITY;
        #pragma unroll
        for (int j = 0; j < 8; j++) {
            rm0 = fmaxf(rm0, fmaxf(s[j][0], s[j][1]));
            rm1 = fmaxf(rm1, fmaxf(s[j][2], s[j][3]));
        }
        rm0 = fmaxf(rm0, __shfl_xor_sync(~0u, rm0, 1)); rm0 = fmaxf(rm0, __shfl_xor_sync(~0u, rm0, 2));
        rm1 = fmaxf(rm1, __shfl_xor_sync(~0u, rm1, 1)); rm1 = fmaxf(rm1, __shfl_xor_sync(~0u, rm1, 2));
        float mn0 = fmaxf(m0r, rm0), mn1 = fmaxf(m1r, rm1);
        float c0 = ex2f(m0r - mn0), c1 = ex2f(m1r - mn1);
        m0r = mn0; m1r = mn1;
        float s0 = 0.f, s1 = 0.f;
        #pragma unroll
        for (int j = 0; j < 8; j++) {
            s[j][0] = ex2f(s[j][0] - mn0); s[j][1] = ex2f(s[j][1] - mn0);
            s[j][2] = ex2f(s[j][2] - mn1); s[j][3] = ex2f(s[j][3] - mn1);
            s0 += s[j][0] + s[j][1]; s1 += s[j][2] + s[j][3];
        }
        s0 += __shfl_xor_sync(~0u, s0, 1); s0 += __shfl_xor_sync(~0u, s0, 2);
        s1 += __shfl_xor_sync(~0u, s1, 1); s1 += __shfl_xor_sync(~0u, s1, 2);
        l0r = l0r * c0 + s0; l1r = l1r * c1 + s1;
        #pragma unroll
        for (int j = 0; j < 8; j++) { O[j][0] *= c0; O[j][1] *= c0; O[j][2] *= c1; O[j][3] *= c1; }

        uint32_t ph[4][4];
        #pragma unroll
        for (int j2 = 0; j2 < 4; j2++) {
            int t0 = 2 * j2, t1 = t0 + 1;
            ph[j2][0] = pack_f16(s[t0][0], s[t0][1]); ph[j2][1] = pack_f16(s[t0][2], s[t0][3]);
            ph[j2][2] = pack_f16(s[t1][0], s[t1][1]); ph[j2][3] = pack_f16(s[t1][2], s[t1][3]);
        }

        #pragma unroll
        for (int j2 = 0; j2 < 4; j2++) {
            uint32_t vh[8][2], r4[4];
            #pragma unroll
            for (int np = 0; np < 4; np++) {
                ldsm4t(r4, vbase + (uint32_t)(j2 * 16 * QS + np * 16) * 2);
                vh[2*np][0]=r4[0]; vh[2*np][1]=r4[1]; vh[2*np+1][0]=r4[2]; vh[2*np+1][1]=r4[3];
            }
            #pragma unroll
            for (int tt = 0; tt < 8; tt++) mma16816(O[tt], ph[j2], vh[tt]);
        }

        uint32_t tmp = cur; cur = nxt; nxt = nn; nn = tmp;
    }

    // epilogue: normalized partial O + per-row (m, l)
    float i0 = 1.f / l0r, i1 = 1.f / l1r;
    const int r0 = q0 + 16 * w + (lid >> 2);
    #pragma unroll
    for (int t = 0; t < 8; t++) {
        int c = h * DK + 8 * t + (lid & 3) * 2;
        #pragma unroll
        for (int hrow = 0; hrow < 2; hrow++) {
            float f0 = O[t][2*hrow]   * (hrow ? i1 : i0);
            float f1 = O[t][2*hrow+1] * (hrow ? i1 : i0);
            size_t dst = (size_t)(r0 + hrow * 8) * DMODEL + c;
            *(uint32_t*)(Oo + dst) = pack_f16(f0, f1);
        }
    }
    if ((lid & 3) == 0) {
        pm[h * S_LEN + r0] = m0r;     pl[h * S_LEN + r0] = l0r;
        pm[h * S_LEN + r0 + 8] = m1r; pl[h * S_LEN + r0 + 8] = l1r;
    }
}

// LSE combine: Ah = (w0*O0 + w1*O1)/(w0+w1), w_i = l_i * exp2(m_i - max(m)).
__global__ void combine(const __half* __restrict__ O0, const __half* __restrict__ O1,
                        const float* __restrict__ pm0, const float* __restrict__ pl0,
                        const float* __restrict__ pm1, const float* __restrict__ pl1,
                        __half* __restrict__ Ah)
{
    int seg = blockIdx.x * blockDim.x + threadIdx.x;   // one 8-elem segment
    if (seg >= XN / 8) return;
    int e = seg * 8;
    int srow = e / DMODEL, c = e - srow * DMODEL;
    int hidx = (c >> 6) * S_LEN + srow;
    float m0 = pm0[hidx], l0 = pl0[hidx], m1 = pm1[hidx], l1 = pl1[hidx];
    float M = fmaxf(m0, m1);
    float w0 = l0 * ex2f(m0 - M), w1 = l1 * ex2f(m1 - M);
    float inv = 1.f / (w0 + w1);
    float a = w0 * inv, b = w1 * inv;
    uint4 u0 = *(const uint4*)(O0 + e);
    uint4 u1 = *(const uint4*)(O1 + e);
    uint4 o;
    uint32_t* pu0 = (uint32_t*)&u0;
    uint32_t* pu1 = (uint32_t*)&u1;
    uint32_t* po  = (uint32_t*)&o;
    #pragma unroll
    for (int i = 0; i < 4; i++) {
        __half2 x = *(__half2*)&pu0[i], y = *(__half2*)&pu1[i];
        po[i] = pack_f16(a * __half2float(x.x) + b * __half2float(y.x),
                         a * __half2float(x.y) + b * __half2float(y.y));
    }
    *(uint4*)(Ah + e) = o;
}

extern "C" void kernel_launch(void* const* d_in, const int* in_sizes, int n_in,
                              void* d_out, int out_size)
{
    const float* q  = (const float*)d_in[0];
    const float* k  = (const float*)d_in[1];
    const float* v  = (const float*)d_in[2];
    const float* Wq = (const float*)d_in[3];
    const float* bq = (const float*)d_in[4];
    const float* Wo = (const float*)d_in[5];
    const float* bo = (const float*)d_in[6];
    float* out = (float*)d_out;

    __half *xh, *wh, *wl, *qh, *kh, *vh, *ah, *p0, *p1;
    float *pm0, *pl0, *pm1, *pl1;
    cudaGetSymbolAddress((void**)&xh, g_xh);
    cudaGetSymbolAddress((void**)&wh, g_wh); cudaGetSymbolAddress((void**)&wl, g_wl);
    cudaGetSymbolAddress((void**)&qh, g_qh);
    cudaGetSymbolAddress((void**)&kh, g_kh); cudaGetSymbolAddress((void**)&vh, g_vh);
    cudaGetSymbolAddress((void**)&ah, g_ah);
    cudaGetSymbolAddress((void**)&p0, g_p0); cudaGetSymbolAddress((void**)&p1, g_p1);
    cudaGetSymbolAddress((void**)&pm0, g_pm0); cudaGetSymbolAddress((void**)&pl0, g_pl0);
    cudaGetSymbolAddress((void**)&pm1, g_pm1); cudaGetSymbolAddress((void**)&pl1, g_pl1);

    cudaFuncSetAttribute(attn_tc,  cudaFuncAttributeMaxDynamicSharedMemorySize, AT_SMEM);
    cudaFuncSetAttribute(qkv_proj, cudaFuncAttributeMaxDynamicSharedMemorySize, QKV_SMEM);
    cudaFuncSetAttribute(out_proj, cudaFuncAttributeMaxDynamicSharedMemorySize, PROJ_SMEM);

    dim3 gc3(XN / 4 / 256, 1, 3);
    conv_hi3<<<gc3, 256>>>(q, k, v, xh, XN / 4);
    dim3 gc2(WN / 4 / 256, 1, 2);
    conv_hilo2<<<gc2, 256>>>(Wq, Wo, wh, wl, WN / 4);

    dim3 gqkv(DMODEL / 128, S_LEN / 128, 3);
    qkv_proj<<<gqkv, 256, QKV_SMEM>>>(xh, wh, bq, qh, kh, vh);

    dim3 gattn(S_LEN / 128 * 2, NH);           // 64 x 12 = 768 jobs (qtile x kvhalf)
    attn_tc<<<gattn, 256, AT_SMEM>>>(qh, kh, vh, p0, p1, pm0, pl0, pm1, pl1);

    combine<<<XN / 8 / 256, 256>>>(p0, p1, pm0, pl0, pm1, pl1, ah);

    dim3 gout(DMODEL / 128, S_LEN / 128);
    out_proj<<<gout, 256, PROJ_SMEM>>>(ah, wh + WN, wl + WN, bo, out);
}